// round 17
// baseline (speedup 1.0000x reference)
#include <cuda_runtime.h>
#include <cuda_bf16.h>
#include <cstdint>

// BitLevelMapper: B=4194304 rows x 16 bits.
// bits:   [B,16] int32 {0,1}  (d_in[0])
// tables: [16, 32768] float32 {0,1} (d_in[1])
// out:    [B,16] float32
//
// R17: R12/R16 structure (best verified, 88.58us) with ONE change — the
// iteration schedule. Instead of grid-stride (each CTA hops 4.75MB per
// iteration; chip-wide scatter over 256MB), each CTA streams a CONTIGUOUS
// 13824-quad (216KB) chunk with stride = blockDim (4KB steps), giving the
// DRAM long sequential read/write runs per SM. CHUNK and nquads are both
// multiples of 256, so every bounds predicate is warp-uniform and the
// shuffle quad path is safe everywhere. Everything else byte-identical.

#define NBITS   16
#define TSIZE   32768           // 2^15 entries per table row
#define NWORDS  2052            // sum over i of ceil(max(2^i,32)/32)

__device__ uint32_t g_packed[NWORDS];

// word offset of table row i in the packed layout
__host__ __device__ __forceinline__ int tab_off(int i) {
    return (i < 5) ? i : ((1 << (i - 5)) + 4);
}

// One warp per packed word: lane b reads entry lw*32+b, ballot packs.
__global__ void pack_tables_kernel(const float* __restrict__ tables) {
    int gw   = (blockIdx.x * blockDim.x + threadIdx.x) >> 5;
    int lane = threadIdx.x & 31;
    if (gw < NWORDS) {
        int i = 0;
        #pragma unroll
        for (int r = 1; r < 16; r++)
            if (gw >= tab_off(r)) i = r;
        int lw = gw - tab_off(i);
        float v = tables[(size_t)i * TSIZE + lw * 32 + lane];
        unsigned word = __ballot_sync(0xffffffffu, v != 0.0f);
        if (lane == 0) g_packed[gw] = word;
    }
    __threadfence();                              // order g_packed before signal
    cudaTriggerProgrammaticLaunchCompletion();    // release dependent launch early
}

#define MAP_BLOCKS  1216        // 152 SMs x 8 CTAs: one full resident wave
#define MAP_THREADS 256
#define CHUNK       13824       // 54 * 256; 1216*13824 >= 16777216

__device__ __forceinline__ float4 quad_out(
    int4 v, int shift, const uint32_t* __restrict__ s_tab)
{
    // partial 16-bit pattern: bit j (array order) sits at position 15-j
    unsigned P = ((unsigned)v.x << shift)       | ((unsigned)v.y << (shift - 1))
               | ((unsigned)v.z << (shift - 2)) | ((unsigned)v.w << (shift - 3));
    // OR-reduce across the aligned 4-lane group -> full pattern in all 4 lanes
    P |= __shfl_xor_sync(0xffffffffu, P, 1);
    P |= __shfl_xor_sync(0xffffffffu, P, 2);

    float o[4];
    #pragma unroll
    for (int m = 0; m < 4; m++) {
        int i = shift - m;                             // table row index
        unsigned addr = P & ((1u << i) - 1u);          // prefix of context
        uint32_t wv = s_tab[tab_off(i) + (addr >> 5)];
        unsigned x = ((wv >> (addr & 31u)) ^ (P >> i)) & 1u;   // bit ^ flip
        o[m] = __uint_as_float((0u - x) & 0x3f800000u);        // x ? 1.0f : 0.0f
    }
    return make_float4(o[0], o[1], o[2], o[3]);
}

__global__ void __launch_bounds__(MAP_THREADS, 8)
map_kernel(const int4* __restrict__ bits4, float4* __restrict__ out4, int nquads) {
    const int start = blockIdx.x * CHUNK;
    // end is a multiple of 256 (CHUNK and nquads both are), so every
    // t < end predicate below is warp-uniform.
    const int end   = (start + CHUNK < nquads) ? (start + CHUNK) : nquads;
    const int tid   = threadIdx.x;
    const int q     = tid & 3;               // quarter within row (lane-group pos)
    const int shift = 15 - 4 * q;            // bit position of v.x in pattern P

    int t0 = start + tid;

    // First input load is independent of the pack — issue it before the
    // dependency sync so the wait overlaps the DRAM fetch. Predicated
    // (warp-uniform) for CTAs whose chunk is empty/short.
    int4 v0;
    bool have0 = (t0 < end);
    if (have0) v0 = bits4[t0];

    cudaGridDependencySynchronize();         // g_packed now valid

    __shared__ uint32_t s_tab[NWORDS];
    for (int t = tid; t < NWORDS; t += blockDim.x)
        s_tab[t] = g_packed[t];
    __syncthreads();

    if (!have0) return;                      // CTA-uniform for empty chunks

    // iteration 0 (peeled, uses the pre-sync load)
    out4[t0] = quad_out(v0, shift, s_tab);

    // contiguous streaming: consecutive iterations advance 4KB
    for (int t = t0 + MAP_THREADS; t < end; t += MAP_THREADS) {
        int4 v = bits4[t];
        out4[t] = quad_out(v, shift, s_tab);
    }
}

extern "C" void kernel_launch(void* const* d_in, const int* in_sizes, int n_in,
                              void* d_out, int out_size) {
    const int4*  bits4  = (const int4*)d_in[0];
    const float* tables = (const float*)d_in[1];
    float4*      out4   = (float4*)d_out;

    int nquads = in_sizes[0] / 4;      // 16777216

    pack_tables_kernel<<<(NWORDS * 32 + 255) / 256, 256>>>(tables);

    cudaLaunchConfig_t cfg = {};
    cfg.gridDim  = dim3(MAP_BLOCKS, 1, 1);
    cfg.blockDim = dim3(MAP_THREADS, 1, 1);
    cfg.dynamicSmemBytes = 0;
    cfg.stream = 0;                    // legacy default stream (capture target)
    cudaLaunchAttribute attr[1];
    attr[0].id = cudaLaunchAttributeProgrammaticStreamSerialization;
    attr[0].val.programmaticStreamSerializationAllowed = 1;
    cfg.attrs = attr;
    cfg.numAttrs = 1;
    cudaLaunchKernelEx(&cfg, map_kernel, bits4, out4, nquads);
}